// round 16
// baseline (speedup 1.0000x reference)
#include <cuda_runtime.h>
#include <cuda_fp16.h>
#include <cstdint>

#define N_NODES 50000
#define N_EDGES 800000
#define E_TOT   (N_EDGES + N_NODES)
#define IN_F    129
#define DEPTH   64                        // max stored degree (Poisson(16): overflow prob ~1e-20)
#define SCAN_B  ((N_NODES + 255) / 256)   // 196
#define GB1     ((N_NODES + 127) / 128)   // 391 gemm blocks
#define CB      ((E_TOT + 255) / 256)     // 3321 fill blocks

// ---------------- scratch (static device globals; no allocation APIs) ----------------
__device__ __align__(16) __half g_x16 [N_NODES * 160];   // x in fp16, zero-padded cols 129..159
__device__ __align__(16) __half g_W1t [128 * 160];       // W1s^T fp16 [n][k], zero k>=129
__device__ __align__(16) __half g_W2t [160 * 128];       // W2^T  fp16 [n][k]
__device__ __align__(16) __half g_h1  [N_NODES * 128];
__device__ __align__(16) __half g_out1[N_NODES * 128];
__device__ __align__(16) __half g_h2  [N_NODES * 160];
__device__ __align__(16) float  g_as1 [N_NODES * 4];
__device__ __align__(16) float  g_ad1 [N_NODES * 4];
__device__ __align__(16) float  g_as2 [N_NODES * 4];
__device__ __align__(16) float  g_ad2 [N_NODES * 4];
__device__ __align__(16) float  g_b1c [128];
__device__ int      g_cnt [N_NODES];
__device__ __align__(16) int g_colv[N_NODES * DEPTH];   // slot k of node d at [d*DEPTH + k]
__device__ unsigned g_maxs[8];
__device__ int      g_is64;

__device__ __forceinline__ unsigned fenc(float f) {
    unsigned u = __float_as_uint(f);
    return (u & 0x80000000u) ? ~u : (u | 0x80000000u);
}
__device__ __forceinline__ float fdec(unsigned e) {
    unsigned u = (e & 0x80000000u) ? (e & 0x7fffffffu) : ~e;
    return __uint_as_float(u);
}

__device__ __forceinline__ int edge_at(const void* ei, long long idx) {
    int v;
    if (g_is64) v = (int)((const long long*)ei)[idx];
    else        v = ((const int*)ei)[idx];
    v = v < 0 ? 0 : v;
    return v >= N_NODES ? N_NODES - 1 : v;
}

// ---------------- fused setup: zero cnt | prep(W1 fold, W2 transpose) | cvt_x ----------------
__global__ void setup_kernel(const int* __restrict__ ei32,
                             const float* __restrict__ x,
                             const float* __restrict__ W1,
                             const float* __restrict__ gamma,
                             const float* __restrict__ beta,
                             const float* __restrict__ mean,
                             const float* __restrict__ var,
                             const float* __restrict__ b1,
                             const float* __restrict__ W2) {
    int b = blockIdx.x;
    if (b < SCAN_B) {
        int i = b * 256 + threadIdx.x;
        if (i < N_NODES) g_cnt[i] = 0;
        if (b == 0) {
            if (threadIdx.x < 32) {
                int bad = 0;
#pragma unroll
                for (int j = 0; j < 4; ++j)
                    if (ei32[1 + 2 * (threadIdx.x * 4 + j)] != 0) bad = 1;
                unsigned bb = __ballot_sync(0xffffffffu, bad);
                if (threadIdx.x == 0) g_is64 = (bb == 0);
            } else if (threadIdx.x < 40) {
                g_maxs[threadIdx.x - 32] = 0x007FFFFFu;   // enc(-inf)
            }
        }
        return;
    }
    b -= SCAN_B;
    if (b < 81) {
        if (b == 0) {
            __shared__ float sc[IN_F], sh[IN_F];
            int t = threadIdx.x;
            for (int k = t; k < IN_F; k += 256) {
                float s = gamma[k] * rsqrtf(var[k] + 1e-5f);
                sc[k] = s;
                sh[k] = beta[k] - mean[k] * s;
            }
            __syncthreads();
            if (t < 128) {
                float acc = b1[t];
#pragma unroll 4
                for (int k = 0; k < IN_F; ++k) {
                    float w0 = W1[k * 128 + t];
                    g_W1t[t * 160 + k] = __float2half(sc[k] * w0);
                    acc = fmaf(sh[k], w0, acc);
                }
                for (int k = IN_F; k < 160; ++k) g_W1t[t * 160 + k] = __half(0.f);
                g_b1c[t] = acc;
            }
        } else {
            int idx = (b - 1) * 256 + threadIdx.x;   // 80*256 = 160*128
            int n = idx >> 7, k = idx & 127;
            g_W2t[n * 128 + k] = __float2half(W2[k * 160 + n]);
        }
        return;
    }
    b -= 81;
    int row  = (b * 256 + threadIdx.x) >> 5;
    int lane = threadIdx.x & 31;
    if (row >= N_NODES) return;
    const float* xr = x + (size_t)row * IN_F;
    __half* o = g_x16 + (size_t)row * 160;
#pragma unroll
    for (int j = 0; j < 3; ++j) {
        int c = j * 64 + lane * 2;
        if (c < 160) {
            float v0 = (c     < IN_F) ? xr[c]     : 0.f;
            float v1 = (c + 1 < IN_F) ? xr[c + 1] : 0.f;
            *reinterpret_cast<__half2*>(o + c) = __floats2half2_rn(v0, v1);
        }
    }
}

// ---------------- fp16 GEMM (cp.async 2-stage, m16n8k16+ldmatrix); LAYER1 grid also fills CSR ----------------
__device__ __forceinline__ uint32_t smem_u32(const void* p) {
    return (uint32_t)__cvta_generic_to_shared(p);
}
__device__ __forceinline__ void cp16(uint32_t dst, const __half* src, bool valid) {
    int sz = valid ? 16 : 0;
    asm volatile("cp.async.cg.shared.global [%0], [%1], 16, %2;"
                 :: "r"(dst), "l"(src), "r"(sz));
}

template<int LAYER>
__global__ __launch_bounds__(256) void gemm_tc_kernel(const float* __restrict__ a_src,
                                                      const float* __restrict__ a_dst,
                                                      const void* __restrict__ ei,
                                                      int M) {
    // ---- CSR slot-fill blocks BEHIND the gemm blocks (layer 1 only) ----
    if (LAYER == 1 && blockIdx.x >= GB1) {
        int e = (blockIdx.x - GB1) * 256 + threadIdx.x;
        if (e < E_TOT) {
            int src, dst;
            if (e < N_EDGES) {
                src = edge_at(ei, e);
                dst = edge_at(ei, (long long)N_EDGES + e);
            } else {
                src = dst = e - N_EDGES;
            }
            int k = atomicAdd(&g_cnt[dst], 1);
            if (k < DEPTH) g_colv[dst * DEPTH + k] = src;
        }
        return;
    }

    constexpr int NC  = (LAYER == 1) ? 128 : 160;
    constexpr int K   = (LAYER == 1) ? IN_F : 128;
    constexpr int BK  = 32;
    constexpr int AP  = BK + 8;
    constexpr int NT  = NC / 8;
    constexpr int NTILES = (K + BK - 1) / BK;
    const __half* Asrc = (LAYER == 1) ? g_x16 : g_out1;
    const __half* Bsrc = (LAYER == 1) ? g_W1t : g_W2t;
    constexpr int ASTR = (LAYER == 1) ? 160 : 128;
    constexpr int BSTR = (LAYER == 1) ? 160 : 128;
    __half*      C = (LAYER == 1) ? g_h1  : g_h2;
    float*   out_s = (LAYER == 1) ? g_as1 : g_as2;
    float*   out_d = (LAYER == 1) ? g_ad1 : g_ad2;
    unsigned* maxs = g_maxs + ((LAYER == 1) ? 0 : 4);

    __shared__ __half As[2][128][AP];
    __shared__ __half Bs[2][NC][AP];
    __shared__ float  smax[8][4];

    int tid  = threadIdx.x;
    int lane = tid & 31;
    int warp = tid >> 5;
    int m0   = warp * 16;
    int qr   = lane >> 2, qc = lane & 3;
    int rowBase = blockIdx.x * 128;

    float acc[NT][4];
#pragma unroll
    for (int nt = 0; nt < NT; ++nt)
#pragma unroll
        for (int j = 0; j < 4; ++j) acc[nt][j] = 0.f;

    int a_row = m0 + (lane & 7) + (lane & 8);
    int a_col = (lane >> 4) << 3;
    int b_row = (lane & 7) + ((lane >> 4) << 3);
    int b_col = lane & 8;

    auto issue = [&](int t) {
        int buf = t & 1;
        int k0  = t * BK;
#pragma unroll
        for (int i = 0; i < 2; ++i) {
            int chunk = tid + i * 256;
            int r = chunk >> 2, c8 = (chunk & 3) * 8;
            int gr = rowBase + r;
            bool v = gr < M;
            cp16(smem_u32(&As[buf][r][c8]),
                 Asrc + (size_t)(v ? gr : 0) * ASTR + k0 + c8, v);
        }
#pragma unroll
        for (int i = 0; i < (NC * 4 + 255) / 256; ++i) {
            int chunk = tid + i * 256;
            if (chunk < NC * 4) {
                int n = chunk >> 2, c8 = (chunk & 3) * 8;
                cp16(smem_u32(&Bs[buf][n][c8]), Bsrc + n * BSTR + k0 + c8, true);
            }
        }
        asm volatile("cp.async.commit_group;");
    };

    issue(0);
    for (int t = 0; t < NTILES; ++t) {
        if (t + 1 < NTILES) {
            issue(t + 1);
            asm volatile("cp.async.wait_group 1;");
        } else {
            asm volatile("cp.async.wait_group 0;");
        }
        __syncthreads();
        int buf = t & 1;
#pragma unroll
        for (int kk16 = 0; kk16 < 2; ++kk16) {
            int kb = kk16 * 16;
            uint32_t a0, a1, a2, a3;
            {
                uint32_t addr = smem_u32(&As[buf][a_row][kb + a_col]);
                asm volatile("ldmatrix.sync.aligned.m8n8.x4.shared.b16 {%0,%1,%2,%3}, [%4];"
                             : "=r"(a0), "=r"(a1), "=r"(a2), "=r"(a3) : "r"(addr));
            }
#pragma unroll
            for (int p = 0; p < NT / 2; ++p) {
                uint32_t b0, b1, b2, b3;
                uint32_t addr = smem_u32(&Bs[buf][p * 16 + b_row][kb + b_col]);
                asm volatile("ldmatrix.sync.aligned.m8n8.x4.shared.b16 {%0,%1,%2,%3}, [%4];"
                             : "=r"(b0), "=r"(b1), "=r"(b2), "=r"(b3) : "r"(addr));
                asm volatile(
                    "mma.sync.aligned.m16n8k16.row.col.f32.f16.f16.f32 "
                    "{%0,%1,%2,%3}, {%4,%5,%6,%7}, {%8,%9}, {%0,%1,%2,%3};"
                    : "+f"(acc[2 * p][0]), "+f"(acc[2 * p][1]),
                      "+f"(acc[2 * p][2]), "+f"(acc[2 * p][3])
                    : "r"(a0), "r"(a1), "r"(a2), "r"(a3), "r"(b0), "r"(b1));
                asm volatile(
                    "mma.sync.aligned.m16n8k16.row.col.f32.f16.f16.f32 "
                    "{%0,%1,%2,%3}, {%4,%5,%6,%7}, {%8,%9}, {%0,%1,%2,%3};"
                    : "+f"(acc[2 * p + 1][0]), "+f"(acc[2 * p + 1][1]),
                      "+f"(acc[2 * p + 1][2]), "+f"(acc[2 * p + 1][3])
                    : "r"(a0), "r"(a1), "r"(a2), "r"(a3), "r"(b2), "r"(b3));
            }
        }
        __syncthreads();
    }

    // ---- epilogue: store h (fp16), per-head alpha dot products, global src max ----
    int gr0 = rowBase + m0 + qr;
    int gr1 = gr0 + 8;
    float ss0[4] = {0,0,0,0}, ss1[4] = {0,0,0,0};
    float dd0[4] = {0,0,0,0}, dd1[4] = {0,0,0,0};
#pragma unroll
    for (int nt = 0; nt < NT; ++nt) {
        int c  = nt * 8 + 2 * qc;
        int hd = (LAYER == 1) ? (nt >> 2) : (nt / 5);
        float b0v = (LAYER == 1) ? g_b1c[c]     : 0.f;
        float b1v = (LAYER == 1) ? g_b1c[c + 1] : 0.f;
        float v00 = acc[nt][0] + b0v, v01 = acc[nt][1] + b1v;
        float v10 = acc[nt][2] + b0v, v11 = acc[nt][3] + b1v;
        if (gr0 < M)
            *reinterpret_cast<__half2*>(&C[(size_t)gr0 * NC + c]) = __floats2half2_rn(v00, v01);
        if (gr1 < M)
            *reinterpret_cast<__half2*>(&C[(size_t)gr1 * NC + c]) = __floats2half2_rn(v10, v11);
        float as0 = a_src[c], as1v = a_src[c + 1];
        float ad0 = a_dst[c], ad1v = a_dst[c + 1];
        ss0[hd] = fmaf(v00, as0, fmaf(v01, as1v, ss0[hd]));
        ss1[hd] = fmaf(v10, as0, fmaf(v11, as1v, ss1[hd]));
        dd0[hd] = fmaf(v00, ad0, fmaf(v01, ad1v, dd0[hd]));
        dd1[hd] = fmaf(v10, ad0, fmaf(v11, ad1v, dd1[hd]));
    }
#pragma unroll
    for (int h = 0; h < 4; ++h) {
#pragma unroll
        for (int off = 2; off; off >>= 1) {
            ss0[h] += __shfl_down_sync(0xffffffffu, ss0[h], off, 4);
            ss1[h] += __shfl_down_sync(0xffffffffu, ss1[h], off, 4);
            dd0[h] += __shfl_down_sync(0xffffffffu, dd0[h], off, 4);
            dd1[h] += __shfl_down_sync(0xffffffffu, dd1[h], off, 4);
        }
    }
    float hm[4];
#pragma unroll
    for (int h = 0; h < 4; ++h) {
        float v = -1e30f;
        if (qc == 0) {
            if (gr0 < M) v = fmaxf(v, ss0[h]);
            if (gr1 < M) v = fmaxf(v, ss1[h]);
        }
#pragma unroll
        for (int off = 16; off; off >>= 1)
            v = fmaxf(v, __shfl_down_sync(0xffffffffu, v, off));
        hm[h] = v;
    }
    if (qc == 0) {
        if (gr0 < M) {
#pragma unroll
            for (int h = 0; h < 4; ++h) {
                out_s[gr0 * 4 + h] = ss0[h];
                out_d[gr0 * 4 + h] = dd0[h];
            }
        }
        if (gr1 < M) {
#pragma unroll
            for (int h = 0; h < 4; ++h) {
                out_s[gr1 * 4 + h] = ss1[h];
                out_d[gr1 * 4 + h] = dd1[h];
            }
        }
    }
    if (lane == 0)
#pragma unroll
        for (int h = 0; h < 4; ++h) smax[warp][h] = hm[h];
    __syncthreads();
    if (tid < 4) {
        float v = -1e30f;
#pragma unroll
        for (int w = 0; w < 8; ++w) v = fmaxf(v, smax[w][tid]);
        atomicMax(&maxs[tid], fenc(v));
    }
}

// ---------------- layer-1 edge pass: scalar loop + src prefetch (low reg cost) ----------------
__global__ void agg1_kernel(const float* __restrict__ bias, int n) {
    int gw   = (blockIdx.x * blockDim.x + threadIdx.x) >> 5;
    int lane = threadIdx.x & 31;
    if (gw >= n) return;
    int hidx = lane >> 3;
    float ad = g_ad1[gw * 4 + hidx];
    float t  = fdec(g_maxs[hidx]) + ad;
    float M  = fmaxf(t, 0.2f * t);
    int deg = min(g_cnt[gw], DEPTH);

    float s = 0.f, a0 = 0.f, a1 = 0.f, a2 = 0.f, a3 = 0.f;
    const uint2* h8 = reinterpret_cast<const uint2*>(g_h1);
    const int* cv = g_colv + gw * DEPTH;
    int srcN = cv[0];
#pragma unroll 4
    for (int k = 0; k < deg; ++k) {
        int src = srcN;
        srcN = cv[min(k + 1, deg - 1)];        // prefetch next index (breaks colv->as chain)
        float e = g_as1[src * 4 + hidx] + ad;
        e = fmaxf(e, 0.2f * e);
        float p = __expf(e - M);
        s += p;
        uint2 raw = h8[src * 32 + lane];
        float2 f01 = __half22float2(*reinterpret_cast<__half2*>(&raw.x));
        float2 f23 = __half22float2(*reinterpret_cast<__half2*>(&raw.y));
        a0 = fmaf(p, f01.x, a0);
        a1 = fmaf(p, f01.y, a1);
        a2 = fmaf(p, f23.x, a2);
        a3 = fmaf(p, f23.y, a3);
    }
    float inv = 1.0f / s;
    float4 bv = reinterpret_cast<const float4*>(bias)[lane];
    float v0 = a0 * inv + bv.x;
    float v1 = a1 * inv + bv.y;
    float v2 = a2 * inv + bv.z;
    float v3 = a3 * inv + bv.w;
    v0 = (v0 > 0.f) ? v0 : expm1f(v0);
    v1 = (v1 > 0.f) ? v1 : expm1f(v1);
    v2 = (v2 > 0.f) ? v2 : expm1f(v2);
    v3 = (v3 > 0.f) ? v3 : expm1f(v3);
    uint2 o;
    *reinterpret_cast<__half2*>(&o.x) = __floats2half2_rn(v0, v1);
    *reinterpret_cast<__half2*>(&o.y) = __floats2half2_rn(v2, v3);
    reinterpret_cast<uint2*>(g_out1)[gw * 32 + lane] = o;
}

// ---------------- layer-2 edge pass: scalar loop + src prefetch ----------------
__global__ void agg2_kernel(const float* __restrict__ bias,
                            float* __restrict__ out, int n) {
    int gw   = (blockIdx.x * blockDim.x + threadIdx.x) >> 5;
    int lane = threadIdx.x & 31;
    if (gw >= n) return;
    bool lo  = lane < 8;
    int h1i  = lane / 10;
    int h2i  = lo ? (32 + lane) / 10 : 3;
    float ad1 = g_ad2[gw * 4 + h1i];
    float ad2 = g_ad2[gw * 4 + h2i];
    float t1 = fdec(g_maxs[4 + h1i]) + ad1;
    float t2 = fdec(g_maxs[4 + h2i]) + ad2;
    float M1 = fmaxf(t1, 0.2f * t1);
    float M2 = fmaxf(t2, 0.2f * t2);
    int deg = min(g_cnt[gw], DEPTH);

    float s1 = 0.f, s2 = 0.f;
    float a0 = 0.f, a1 = 0.f, a2 = 0.f, a3 = 0.f;
    float b0 = 0.f, b1 = 0.f, b2 = 0.f, b3 = 0.f;
    const uint2* h8 = reinterpret_cast<const uint2*>(g_h2);
    const int* cv = g_colv + gw * DEPTH;
    int srcN = cv[0];
#pragma unroll 2
    for (int k = 0; k < deg; ++k) {
        int src = srcN;
        srcN = cv[min(k + 1, deg - 1)];        // prefetch next index
        float ea = g_as2[src * 4 + h1i] + ad1;
        float eb = g_as2[src * 4 + h2i] + ad2;
        ea = fmaxf(ea, 0.2f * ea);
        eb = fmaxf(eb, 0.2f * eb);
        float p1 = __expf(ea - M1);
        float p2 = __expf(eb - M2);
        s1 += p1; s2 += p2;
        uint2 raw = h8[src * 40 + lane];
        float2 f01 = __half22float2(*reinterpret_cast<__half2*>(&raw.x));
        float2 f23 = __half22float2(*reinterpret_cast<__half2*>(&raw.y));
        a0 = fmaf(p1, f01.x, a0);
        a1 = fmaf(p1, f01.y, a1);
        a2 = fmaf(p1, f23.x, a2);
        a3 = fmaf(p1, f23.y, a3);
        if (lo) {
            uint2 rw = h8[src * 40 + 32 + lane];
            float2 g01 = __half22float2(*reinterpret_cast<__half2*>(&rw.x));
            float2 g23 = __half22float2(*reinterpret_cast<__half2*>(&rw.y));
            b0 = fmaf(p2, g01.x, b0);
            b1 = fmaf(p2, g01.y, b1);
            b2 = fmaf(p2, g23.x, b2);
            b3 = fmaf(p2, g23.y, b3);
        }
    }
    float inv1 = 1.0f / s1;
    float4 bv = reinterpret_cast<const float4*>(bias)[lane];
    reinterpret_cast<float4*>(out)[(size_t)gw * 40 + lane] =
        make_float4(a0 * inv1 + bv.x, a1 * inv1 + bv.y,
                    a2 * inv1 + bv.z, a3 * inv1 + bv.w);
    if (lo) {
        float inv2 = 1.0f / s2;
        float4 bw = reinterpret_cast<const float4*>(bias)[32 + lane];
        reinterpret_cast<float4*>(out)[(size_t)gw * 40 + 32 + lane] =
            make_float4(b0 * inv2 + bw.x, b1 * inv2 + bw.y,
                        b2 * inv2 + bw.z, b3 * inv2 + bw.w);
    }
}

// ---------------- launch ----------------
extern "C" void kernel_launch(void* const* d_in, const int* in_sizes, int n_in,
                              void* d_out, int out_size) {
    const float* x      = (const float*)d_in[0];
    const void*  ei     = d_in[1];
    const float* gamma  = (const float*)d_in[2];
    const float* beta   = (const float*)d_in[3];
    const float* mean   = (const float*)d_in[4];
    const float* var    = (const float*)d_in[5];
    const float* W1     = (const float*)d_in[6];
    const float* a1_src = (const float*)d_in[7];
    const float* a1_dst = (const float*)d_in[8];
    const float* b1     = (const float*)d_in[9];
    const float* W2     = (const float*)d_in[10];
    const float* a2_src = (const float*)d_in[11];
    const float* a2_dst = (const float*)d_in[12];
    const float* b2     = (const float*)d_in[13];
    float*       out    = (float*)d_out;

    const int NWB = 6250;
    const int SETUP_B = SCAN_B + 81 + (N_NODES * 32 + 255) / 256;

    setup_kernel<<<SETUP_B, 256>>>((const int*)ei, x, W1, gamma, beta, mean, var, b1, W2); // 0
    gemm_tc_kernel<1><<<GB1 + CB, 256>>>(a1_src, a1_dst, ei, N_NODES);                     // 1 gemm1 + CSR fill
    agg1_kernel<<<NWB, 256>>>(b1, N_NODES);                                                // 2
    gemm_tc_kernel<2><<<GB1, 256>>>(a2_src, a2_dst, ei, N_NODES);                          // 3
    agg2_kernel<<<NWB, 256>>>(b2, out, N_NODES);                                           // 4
}

// round 17
// speedup vs baseline: 1.0773x; 1.0773x over previous
#include <cuda_runtime.h>
#include <cuda_fp16.h>
#include <cstdint>

#define N_NODES 50000
#define N_EDGES 800000
#define E_TOT   (N_EDGES + N_NODES)
#define IN_F    129
#define DEPTH   64                        // max stored degree (Poisson(16): overflow prob ~1e-20)
#define SCAN_B  ((N_NODES + 255) / 256)   // 196
#define GB1     ((N_NODES + 127) / 128)   // 391 gemm blocks
#define CB      ((E_TOT + 255) / 256)     // 3321 fill blocks

// ---------------- scratch (static device globals; no allocation APIs) ----------------
__device__ __align__(16) __half g_x16 [N_NODES * 160];   // x in fp16, zero-padded cols 129..159
__device__ __align__(16) __half g_W1t [128 * 160];       // W1s^T fp16 [n][k], zero k>=129
__device__ __align__(16) __half g_W2t [160 * 128];       // W2^T  fp16 [n][k]
__device__ __align__(16) __half g_h1  [N_NODES * 128];
__device__ __align__(16) __half g_out1[N_NODES * 128];
__device__ __align__(16) __half g_h2  [N_NODES * 160];
__device__ __align__(16) float  g_as1 [N_NODES * 4];
__device__ __align__(16) float  g_ad1 [N_NODES * 4];
__device__ __align__(16) float  g_as2 [N_NODES * 4];
__device__ __align__(16) float  g_ad2 [N_NODES * 4];
__device__ __align__(16) float  g_b1c [128];
__device__ int      g_cnt [N_NODES];
__device__ __align__(16) int g_colv[N_NODES * DEPTH];   // slot k of node d at [d*DEPTH + k]
__device__ unsigned g_maxs[8];
__device__ int      g_is64;

__device__ __forceinline__ unsigned fenc(float f) {
    unsigned u = __float_as_uint(f);
    return (u & 0x80000000u) ? ~u : (u | 0x80000000u);
}
__device__ __forceinline__ float fdec(unsigned e) {
    unsigned u = (e & 0x80000000u) ? (e & 0x7fffffffu) : ~e;
    return __uint_as_float(u);
}

__device__ __forceinline__ int edge_at(const void* ei, long long idx) {
    int v;
    if (g_is64) v = (int)((const long long*)ei)[idx];
    else        v = ((const int*)ei)[idx];
    v = v < 0 ? 0 : v;
    return v >= N_NODES ? N_NODES - 1 : v;
}

// ---------------- fused setup: zero cnt | prep(W1 fold, W2 transpose) | cvt_x ----------------
__global__ void setup_kernel(const int* __restrict__ ei32,
                             const float* __restrict__ x,
                             const float* __restrict__ W1,
                             const float* __restrict__ gamma,
                             const float* __restrict__ beta,
                             const float* __restrict__ mean,
                             const float* __restrict__ var,
                             const float* __restrict__ b1,
                             const float* __restrict__ W2) {
    int b = blockIdx.x;
    if (b < SCAN_B) {
        int i = b * 256 + threadIdx.x;
        if (i < N_NODES) g_cnt[i] = 0;
        if (b == 0) {
            if (threadIdx.x < 32) {
                int bad = 0;
#pragma unroll
                for (int j = 0; j < 4; ++j)
                    if (ei32[1 + 2 * (threadIdx.x * 4 + j)] != 0) bad = 1;
                unsigned bb = __ballot_sync(0xffffffffu, bad);
                if (threadIdx.x == 0) g_is64 = (bb == 0);
            } else if (threadIdx.x < 40) {
                g_maxs[threadIdx.x - 32] = 0x007FFFFFu;   // enc(-inf)
            }
        }
        return;
    }
    b -= SCAN_B;
    if (b < 81) {
        if (b == 0) {
            __shared__ float sc[IN_F], sh[IN_F];
            int t = threadIdx.x;
            for (int k = t; k < IN_F; k += 256) {
                float s = gamma[k] * rsqrtf(var[k] + 1e-5f);
                sc[k] = s;
                sh[k] = beta[k] - mean[k] * s;
            }
            __syncthreads();
            if (t < 128) {
                float acc = b1[t];
#pragma unroll 4
                for (int k = 0; k < IN_F; ++k) {
                    float w0 = W1[k * 128 + t];
                    g_W1t[t * 160 + k] = __float2half(sc[k] * w0);
                    acc = fmaf(sh[k], w0, acc);
                }
                for (int k = IN_F; k < 160; ++k) g_W1t[t * 160 + k] = __half(0.f);
                g_b1c[t] = acc;
            }
        } else {
            int idx = (b - 1) * 256 + threadIdx.x;   // 80*256 = 160*128
            int n = idx >> 7, k = idx & 127;
            g_W2t[n * 128 + k] = __float2half(W2[k * 160 + n]);
        }
        return;
    }
    b -= 81;
    int row  = (b * 256 + threadIdx.x) >> 5;
    int lane = threadIdx.x & 31;
    if (row >= N_NODES) return;
    const float* xr = x + (size_t)row * IN_F;
    __half* o = g_x16 + (size_t)row * 160;
#pragma unroll
    for (int j = 0; j < 3; ++j) {
        int c = j * 64 + lane * 2;
        if (c < 160) {
            float v0 = (c     < IN_F) ? xr[c]     : 0.f;
            float v1 = (c + 1 < IN_F) ? xr[c + 1] : 0.f;
            *reinterpret_cast<__half2*>(o + c) = __floats2half2_rn(v0, v1);
        }
    }
}

// ---------------- fp16 GEMM (cp.async 2-stage, m16n8k16+ldmatrix); LAYER1 grid also fills CSR ----------------
__device__ __forceinline__ uint32_t smem_u32(const void* p) {
    return (uint32_t)__cvta_generic_to_shared(p);
}
__device__ __forceinline__ void cp16(uint32_t dst, const __half* src, bool valid) {
    int sz = valid ? 16 : 0;
    asm volatile("cp.async.cg.shared.global [%0], [%1], 16, %2;"
                 :: "r"(dst), "l"(src), "r"(sz));
}

template<int LAYER>
__global__ __launch_bounds__(256) void gemm_tc_kernel(const float* __restrict__ a_src,
                                                      const float* __restrict__ a_dst,
                                                      const void* __restrict__ ei,
                                                      int M) {
    // ---- CSR slot-fill blocks BEHIND the gemm blocks (layer 1 only) ----
    if (LAYER == 1 && blockIdx.x >= GB1) {
        int e = (blockIdx.x - GB1) * 256 + threadIdx.x;
        if (e < E_TOT) {
            int src, dst;
            if (e < N_EDGES) {
                src = edge_at(ei, e);
                dst = edge_at(ei, (long long)N_EDGES + e);
            } else {
                src = dst = e - N_EDGES;
            }
            int k = atomicAdd(&g_cnt[dst], 1);
            if (k < DEPTH) g_colv[dst * DEPTH + k] = src;
        }
        return;
    }

    constexpr int NC  = (LAYER == 1) ? 128 : 160;
    constexpr int K   = (LAYER == 1) ? IN_F : 128;
    constexpr int BK  = 32;
    constexpr int AP  = BK + 8;
    constexpr int NT  = NC / 8;
    constexpr int NTILES = (K + BK - 1) / BK;
    const __half* Asrc = (LAYER == 1) ? g_x16 : g_out1;
    const __half* Bsrc = (LAYER == 1) ? g_W1t : g_W2t;
    constexpr int ASTR = (LAYER == 1) ? 160 : 128;
    constexpr int BSTR = (LAYER == 1) ? 160 : 128;
    __half*      C = (LAYER == 1) ? g_h1  : g_h2;
    float*   out_s = (LAYER == 1) ? g_as1 : g_as2;
    float*   out_d = (LAYER == 1) ? g_ad1 : g_ad2;
    unsigned* maxs = g_maxs + ((LAYER == 1) ? 0 : 4);

    __shared__ __half As[2][128][AP];
    __shared__ __half Bs[2][NC][AP];
    __shared__ float  smax[8][4];

    int tid  = threadIdx.x;
    int lane = tid & 31;
    int warp = tid >> 5;
    int m0   = warp * 16;
    int qr   = lane >> 2, qc = lane & 3;
    int rowBase = blockIdx.x * 128;

    float acc[NT][4];
#pragma unroll
    for (int nt = 0; nt < NT; ++nt)
#pragma unroll
        for (int j = 0; j < 4; ++j) acc[nt][j] = 0.f;

    int a_row = m0 + (lane & 7) + (lane & 8);
    int a_col = (lane >> 4) << 3;
    int b_row = (lane & 7) + ((lane >> 4) << 3);
    int b_col = lane & 8;

    auto issue = [&](int t) {
        int buf = t & 1;
        int k0  = t * BK;
#pragma unroll
        for (int i = 0; i < 2; ++i) {
            int chunk = tid + i * 256;
            int r = chunk >> 2, c8 = (chunk & 3) * 8;
            int gr = rowBase + r;
            bool v = gr < M;
            cp16(smem_u32(&As[buf][r][c8]),
                 Asrc + (size_t)(v ? gr : 0) * ASTR + k0 + c8, v);
        }
#pragma unroll
        for (int i = 0; i < (NC * 4 + 255) / 256; ++i) {
            int chunk = tid + i * 256;
            if (chunk < NC * 4) {
                int n = chunk >> 2, c8 = (chunk & 3) * 8;
                cp16(smem_u32(&Bs[buf][n][c8]), Bsrc + n * BSTR + k0 + c8, true);
            }
        }
        asm volatile("cp.async.commit_group;");
    };

    issue(0);
    for (int t = 0; t < NTILES; ++t) {
        if (t + 1 < NTILES) {
            issue(t + 1);
            asm volatile("cp.async.wait_group 1;");
        } else {
            asm volatile("cp.async.wait_group 0;");
        }
        __syncthreads();
        int buf = t & 1;
#pragma unroll
        for (int kk16 = 0; kk16 < 2; ++kk16) {
            int kb = kk16 * 16;
            uint32_t a0, a1, a2, a3;
            {
                uint32_t addr = smem_u32(&As[buf][a_row][kb + a_col]);
                asm volatile("ldmatrix.sync.aligned.m8n8.x4.shared.b16 {%0,%1,%2,%3}, [%4];"
                             : "=r"(a0), "=r"(a1), "=r"(a2), "=r"(a3) : "r"(addr));
            }
#pragma unroll
            for (int p = 0; p < NT / 2; ++p) {
                uint32_t b0, b1, b2, b3;
                uint32_t addr = smem_u32(&Bs[buf][p * 16 + b_row][kb + b_col]);
                asm volatile("ldmatrix.sync.aligned.m8n8.x4.shared.b16 {%0,%1,%2,%3}, [%4];"
                             : "=r"(b0), "=r"(b1), "=r"(b2), "=r"(b3) : "r"(addr));
                asm volatile(
                    "mma.sync.aligned.m16n8k16.row.col.f32.f16.f16.f32 "
                    "{%0,%1,%2,%3}, {%4,%5,%6,%7}, {%8,%9}, {%0,%1,%2,%3};"
                    : "+f"(acc[2 * p][0]), "+f"(acc[2 * p][1]),
                      "+f"(acc[2 * p][2]), "+f"(acc[2 * p][3])
                    : "r"(a0), "r"(a1), "r"(a2), "r"(a3), "r"(b0), "r"(b1));
                asm volatile(
                    "mma.sync.aligned.m16n8k16.row.col.f32.f16.f16.f32 "
                    "{%0,%1,%2,%3}, {%4,%5,%6,%7}, {%8,%9}, {%0,%1,%2,%3};"
                    : "+f"(acc[2 * p + 1][0]), "+f"(acc[2 * p + 1][1]),
                      "+f"(acc[2 * p + 1][2]), "+f"(acc[2 * p + 1][3])
                    : "r"(a0), "r"(a1), "r"(a2), "r"(a3), "r"(b2), "r"(b3));
            }
        }
        __syncthreads();
    }

    // ---- epilogue: store h (fp16), per-head alpha dot products, global src max ----
    int gr0 = rowBase + m0 + qr;
    int gr1 = gr0 + 8;
    float ss0[4] = {0,0,0,0}, ss1[4] = {0,0,0,0};
    float dd0[4] = {0,0,0,0}, dd1[4] = {0,0,0,0};
#pragma unroll
    for (int nt = 0; nt < NT; ++nt) {
        int c  = nt * 8 + 2 * qc;
        int hd = (LAYER == 1) ? (nt >> 2) : (nt / 5);
        float b0v = (LAYER == 1) ? g_b1c[c]     : 0.f;
        float b1v = (LAYER == 1) ? g_b1c[c + 1] : 0.f;
        float v00 = acc[nt][0] + b0v, v01 = acc[nt][1] + b1v;
        float v10 = acc[nt][2] + b0v, v11 = acc[nt][3] + b1v;
        if (gr0 < M)
            *reinterpret_cast<__half2*>(&C[(size_t)gr0 * NC + c]) = __floats2half2_rn(v00, v01);
        if (gr1 < M)
            *reinterpret_cast<__half2*>(&C[(size_t)gr1 * NC + c]) = __floats2half2_rn(v10, v11);
        float as0 = a_src[c], as1v = a_src[c + 1];
        float ad0 = a_dst[c], ad1v = a_dst[c + 1];
        ss0[hd] = fmaf(v00, as0, fmaf(v01, as1v, ss0[hd]));
        ss1[hd] = fmaf(v10, as0, fmaf(v11, as1v, ss1[hd]));
        dd0[hd] = fmaf(v00, ad0, fmaf(v01, ad1v, dd0[hd]));
        dd1[hd] = fmaf(v10, ad0, fmaf(v11, ad1v, dd1[hd]));
    }
#pragma unroll
    for (int h = 0; h < 4; ++h) {
#pragma unroll
        for (int off = 2; off; off >>= 1) {
            ss0[h] += __shfl_down_sync(0xffffffffu, ss0[h], off, 4);
            ss1[h] += __shfl_down_sync(0xffffffffu, ss1[h], off, 4);
            dd0[h] += __shfl_down_sync(0xffffffffu, dd0[h], off, 4);
            dd1[h] += __shfl_down_sync(0xffffffffu, dd1[h], off, 4);
        }
    }
    float hm[4];
#pragma unroll
    for (int h = 0; h < 4; ++h) {
        float v = -1e30f;
        if (qc == 0) {
            if (gr0 < M) v = fmaxf(v, ss0[h]);
            if (gr1 < M) v = fmaxf(v, ss1[h]);
        }
#pragma unroll
        for (int off = 16; off; off >>= 1)
            v = fmaxf(v, __shfl_down_sync(0xffffffffu, v, off));
        hm[h] = v;
    }
    if (qc == 0) {
        if (gr0 < M) {
#pragma unroll
            for (int h = 0; h < 4; ++h) {
                out_s[gr0 * 4 + h] = ss0[h];
                out_d[gr0 * 4 + h] = dd0[h];
            }
        }
        if (gr1 < M) {
#pragma unroll
            for (int h = 0; h < 4; ++h) {
                out_s[gr1 * 4 + h] = ss1[h];
                out_d[gr1 * 4 + h] = dd1[h];
            }
        }
    }
    if (lane == 0)
#pragma unroll
        for (int h = 0; h < 4; ++h) smax[warp][h] = hm[h];
    __syncthreads();
    if (tid < 4) {
        float v = -1e30f;
#pragma unroll
        for (int w = 0; w < 8; ++w) v = fmaxf(v, smax[w][tid]);
        atomicMax(&maxs[tid], fenc(v));
    }
}

// ---------------- layer-1 edge pass (R14 form; __ldg on read-only gathers) ----------------
__global__ void agg1_kernel(const float* __restrict__ bias, int n) {
    int gw   = (blockIdx.x * blockDim.x + threadIdx.x) >> 5;
    int lane = threadIdx.x & 31;
    if (gw >= n) return;
    int hidx = lane >> 3;
    float ad = g_ad1[gw * 4 + hidx];
    float t  = fdec(g_maxs[hidx]) + ad;
    float M  = fmaxf(t, 0.2f * t);
    int deg = min(g_cnt[gw], DEPTH);

    float s = 0.f, a0 = 0.f, a1 = 0.f, a2 = 0.f, a3 = 0.f;
    const uint2* h8 = reinterpret_cast<const uint2*>(g_h1);
    const int* cv = g_colv + gw * DEPTH;
#pragma unroll 4
    for (int k = 0; k < deg; ++k) {
        int src = __ldg(cv + k);
        float e = __ldg(g_as1 + src * 4 + hidx) + ad;
        e = fmaxf(e, 0.2f * e);
        float p = __expf(e - M);
        s += p;
        uint2 raw = __ldg(h8 + src * 32 + lane);
        float2 f01 = __half22float2(*reinterpret_cast<__half2*>(&raw.x));
        float2 f23 = __half22float2(*reinterpret_cast<__half2*>(&raw.y));
        a0 = fmaf(p, f01.x, a0);
        a1 = fmaf(p, f01.y, a1);
        a2 = fmaf(p, f23.x, a2);
        a3 = fmaf(p, f23.y, a3);
    }
    float inv = 1.0f / s;
    float4 bv = reinterpret_cast<const float4*>(bias)[lane];
    float v0 = a0 * inv + bv.x;
    float v1 = a1 * inv + bv.y;
    float v2 = a2 * inv + bv.z;
    float v3 = a3 * inv + bv.w;
    v0 = (v0 > 0.f) ? v0 : expm1f(v0);
    v1 = (v1 > 0.f) ? v1 : expm1f(v1);
    v2 = (v2 > 0.f) ? v2 : expm1f(v2);
    v3 = (v3 > 0.f) ? v3 : expm1f(v3);
    uint2 o;
    *reinterpret_cast<__half2*>(&o.x) = __floats2half2_rn(v0, v1);
    *reinterpret_cast<__half2*>(&o.y) = __floats2half2_rn(v2, v3);
    reinterpret_cast<uint2*>(g_out1)[gw * 32 + lane] = o;
}

// ---------------- layer-2 edge pass (R14 form; __ldg on read-only gathers) ----------------
__global__ void agg2_kernel(const float* __restrict__ bias,
                            float* __restrict__ out, int n) {
    int gw   = (blockIdx.x * blockDim.x + threadIdx.x) >> 5;
    int lane = threadIdx.x & 31;
    if (gw >= n) return;
    bool lo  = lane < 8;
    int h1i  = lane / 10;
    int h2i  = lo ? (32 + lane) / 10 : 3;
    float ad1 = g_ad2[gw * 4 + h1i];
    float ad2 = g_ad2[gw * 4 + h2i];
    float t1 = fdec(g_maxs[4 + h1i]) + ad1;
    float t2 = fdec(g_maxs[4 + h2i]) + ad2;
    float M1 = fmaxf(t1, 0.2f * t1);
    float M2 = fmaxf(t2, 0.2f * t2);
    int deg = min(g_cnt[gw], DEPTH);

    float s1 = 0.f, s2 = 0.f;
    float a0 = 0.f, a1 = 0.f, a2 = 0.f, a3 = 0.f;
    float b0 = 0.f, b1 = 0.f, b2 = 0.f, b3 = 0.f;
    const uint2* h8 = reinterpret_cast<const uint2*>(g_h2);
    const int* cv = g_colv + gw * DEPTH;
#pragma unroll 2
    for (int k = 0; k < deg; ++k) {
        int src = __ldg(cv + k);
        float ea = __ldg(g_as2 + src * 4 + h1i) + ad1;
        float eb = __ldg(g_as2 + src * 4 + h2i) + ad2;
        ea = fmaxf(ea, 0.2f * ea);
        eb = fmaxf(eb, 0.2f * eb);
        float p1 = __expf(ea - M1);
        float p2 = __expf(eb - M2);
        s1 += p1; s2 += p2;
        uint2 raw = __ldg(h8 + src * 40 + lane);
        float2 f01 = __half22float2(*reinterpret_cast<__half2*>(&raw.x));
        float2 f23 = __half22float2(*reinterpret_cast<__half2*>(&raw.y));
        a0 = fmaf(p1, f01.x, a0);
        a1 = fmaf(p1, f01.y, a1);
        a2 = fmaf(p1, f23.x, a2);
        a3 = fmaf(p1, f23.y, a3);
        if (lo) {
            uint2 rw = __ldg(h8 + src * 40 + 32 + lane);
            float2 g01 = __half22float2(*reinterpret_cast<__half2*>(&rw.x));
            float2 g23 = __half22float2(*reinterpret_cast<__half2*>(&rw.y));
            b0 = fmaf(p2, g01.x, b0);
            b1 = fmaf(p2, g01.y, b1);
            b2 = fmaf(p2, g23.x, b2);
            b3 = fmaf(p2, g23.y, b3);
        }
    }
    float inv1 = 1.0f / s1;
    float4 bv = reinterpret_cast<const float4*>(bias)[lane];
    reinterpret_cast<float4*>(out)[(size_t)gw * 40 + lane] =
        make_float4(a0 * inv1 + bv.x, a1 * inv1 + bv.y,
                    a2 * inv1 + bv.z, a3 * inv1 + bv.w);
    if (lo) {
        float inv2 = 1.0f / s2;
        float4 bw = reinterpret_cast<const float4*>(bias)[32 + lane];
        reinterpret_cast<float4*>(out)[(size_t)gw * 40 + 32 + lane] =
            make_float4(b0 * inv2 + bw.x, b1 * inv2 + bw.y,
                        b2 * inv2 + bw.z, b3 * inv2 + bw.w);
    }
}

// ---------------- launch ----------------
extern "C" void kernel_launch(void* const* d_in, const int* in_sizes, int n_in,
                              void* d_out, int out_size) {
    const float* x      = (const float*)d_in[0];
    const void*  ei     = d_in[1];
    const float* gamma  = (const float*)d_in[2];
    const float* beta   = (const float*)d_in[3];
    const float* mean   = (const float*)d_in[4];
    const float* var    = (const float*)d_in[5];
    const float* W1     = (const float*)d_in[6];
    const float* a1_src = (const float*)d_in[7];
    const float* a1_dst = (const float*)d_in[8];
    const float* b1     = (const float*)d_in[9];
    const float* W2     = (const float*)d_in[10];
    const float* a2_src = (const float*)d_in[11];
    const float* a2_dst = (const float*)d_in[12];
    const float* b2     = (const float*)d_in[13];
    float*       out    = (float*)d_out;

    const int NWB = 6250;
    const int SETUP_B = SCAN_B + 81 + (N_NODES * 32 + 255) / 256;

    setup_kernel<<<SETUP_B, 256>>>((const int*)ei, x, W1, gamma, beta, mean, var, b1, W2); // 0
    gemm_tc_kernel<1><<<GB1 + CB, 256>>>(a1_src, a1_dst, ei, N_NODES);                     // 1 gemm1 + CSR fill
    agg1_kernel<<<NWB, 256>>>(b1, N_NODES);                                                // 2
    gemm_tc_kernel<2><<<GB1, 256>>>(a2_src, a2_dst, ei, N_NODES);                          // 3
    agg2_kernel<<<NWB, 256>>>(b2, out, N_NODES);                                           // 4
}